// round 2
// baseline (speedup 1.0000x reference)
#include <cuda_runtime.h>
#include <math.h>

#define HD 256
#define DD 64

// Prep scratch: transposed weights for coalesced access in the fused kernel.
__device__ float g_W1T[2 * DD * HD];   // [pass][(j*64 + m)]  (j hidden, m input)
__device__ float g_W2T[2 * HD * HD];   // [pass][(k*256 + j)]

__global__ void prep_kernel(const float* __restrict__ W1m, const float* __restrict__ W2m,
                            const float* __restrict__ W1q, const float* __restrict__ W2q)
{
    int t = blockIdx.x * blockDim.x + threadIdx.x;
    if (t < DD * HD) {
        int j = t >> 6, m = t & 63;
        g_W1T[t]           = W1m[m * HD + j];
        g_W1T[DD * HD + t] = W1q[m * HD + j];
    }
    if (t < HD * HD) {
        int k = t >> 8, j = t & 255;
        g_W2T[t]           = W2m[j * HD + k];
        g_W2T[HD * HD + t] = W2q[j * HD + k];
    }
}

// Shared memory layout (floats):
//   MsT   [256][68]   17408   M transposed (k-major), padded
//   Bs    [16][256]    4096   W2 j-tile for M GEMM
//   Ast   [16][64]     1024   scaled W1T tile (also reused as W1T tile in H1)
//   Hs    [32][68]     2176   Hessian rows 32..63 (accumulated over both MLPs)
//   h1s,aas,sss,ccs,ees,dds,aus : 7*256
//   xs[64], gsA[64], gpart[256], Sv[32*34]
#define SMEM_FLOATS (17408 + 4096 + 1024 + 2176 + 7*256 + 64 + 64 + 256 + 32*34)
#define SMEM_BYTES  (SMEM_FLOATS * 4)

__global__ __launch_bounds__(256, 2)
void lnn_kernel(const float* __restrict__ x,
                const float* __restrict__ W1m, const float* __restrict__ b1m,
                const float* __restrict__ W2m, const float* __restrict__ b2m,
                const float* __restrict__ W3m,
                const float* __restrict__ W1q, const float* __restrict__ b1q,
                const float* __restrict__ W2q, const float* __restrict__ b2q,
                const float* __restrict__ W3q,
                float* __restrict__ out)
{
    extern __shared__ float sm[];
    float* MsT   = sm;                 // 17408
    float* Bs    = MsT + 17408;        // 4096
    float* Ast   = Bs + 4096;          // 1024
    float* Hs    = Ast + 1024;         // 2176
    float* h1s   = Hs + 2176;          // 256
    float* aas   = h1s + 256;
    float* sss   = aas + 256;
    float* ccs   = sss + 256;
    float* ees   = ccs + 256;
    float* dds   = ees + 256;
    float* aus   = dds + 256;
    float* xs    = aus + 256;          // 64
    float* gsA   = xs + 64;            // 64
    float* gpart = gsA + 64;           // 256
    float* Sv    = gpart + 256;        // 1088

    const int tid = threadIdx.x;
    const int b   = blockIdx.x;

    for (int q = tid; q < 2176; q += 256) Hs[q] = 0.0f;
    if (tid < 64) { gsA[tid] = 0.0f; xs[tid] = x[b * 64 + tid]; }
    __syncthreads();

    #pragma unroll 1
    for (int pass = 0; pass < 2; pass++) {
        const float* W1  = pass ? W1q : W1m;
        const float* b1  = pass ? b1q : b1m;
        const float* W2  = pass ? W2q : W2m;
        const float* b2  = pass ? b2q : b2m;
        const float* W3  = pass ? W3q : W3m;
        const float* W1T = g_W1T + pass * (DD * HD);
        const float* W2T = g_W2T + pass * (HD * HD);

        // ---- Stage 1: z1 = x W1 + b1 ; h1, a = act', s = act'' ----
        {
            int j = tid;
            float z = b1[j];
            #pragma unroll 8
            for (int i = 0; i < 64; i++) z = fmaf(xs[i], W1[i * HD + j], z);
            float h, a, s;
            if (pass == 0) {
                float sg = 1.0f / (1.0f + __expf(-z));
                h = fmaxf(z, 0.0f) + log1pf(__expf(-fabsf(z)));
                a = sg;
                s = sg * (1.0f - sg);
            } else {
                float t = tanhf(0.5f * z);
                float o = 1.0f - t * t;
                h = z * t;
                a = fmaf(0.5f * z, o, t);
                s = o * (1.0f - 0.5f * z * t);
            }
            h1s[j] = h; aas[j] = a; sss[j] = s;
        }
        __syncthreads();

        // ---- Stage 2: z2 = h1 W2 + b2 ; c = act'(z2)*w3, e = act''(z2)*w3 ----
        {
            int k = tid;
            float z = b2[k];
            #pragma unroll 8
            for (int l = 0; l < 256; l++) z = fmaf(h1s[l], W2[l * HD + k], z);
            float a, s;
            if (pass == 0) {
                float sg = 1.0f / (1.0f + __expf(-z));
                a = sg;
                s = sg * (1.0f - sg);
            } else {
                float t = tanhf(0.5f * z);
                float o = 1.0f - t * t;
                a = fmaf(0.5f * z, o, t);
                s = o * (1.0f - 0.5f * z * t);
            }
            float w3v = W3[k];
            ccs[k] = a * w3v;
            ees[k] = s * w3v;
        }
        __syncthreads();

        // ---- Stage 3: u = W2 c ; d = s*u, au = a*u ----
        {
            int j = tid;
            float u = 0.0f;
            #pragma unroll 8
            for (int k = 0; k < 256; k++) u = fmaf(ccs[k], W2T[k * HD + j], u);
            dds[j] = sss[j] * u;
            aus[j] = aas[j] * u;
        }
        __syncthreads();

        // ---- Stage 4: gradient g = W1 (a*u), 4-way j-split ----
        {
            int m = tid & 63, part = tid >> 6;
            const float* W1Tp = W1T + part * 64 * 64;
            const float* ausp = aus + part * 64;
            float gp = 0.0f;
            #pragma unroll 8
            for (int jj = 0; jj < 64; jj++) gp = fmaf(W1Tp[jj * 64 + m], ausp[jj], gp);
            gpart[part * 64 + m] = gp;
        }
        __syncthreads();
        if (tid < 64)
            gsA[tid] += gpart[tid] + gpart[64 + tid] + gpart[128 + tid] + gpart[192 + tid];

        // ---- Stage 5: M = (W1 . a) W2  ->  MsT[k][m] (k-major) ----
        {
            const int tk = tid >> 3;   // 0..31 -> k tile *8
            const int tm = tid & 7;    // 0..7  -> m tile *8
            float acc[8][8];
            #pragma unroll
            for (int i = 0; i < 8; i++)
                #pragma unroll
                for (int j = 0; j < 8; j++) acc[i][j] = 0.0f;

            const float4* W2v  = (const float4*)W2;
            const float4* W1Tv = (const float4*)W1T;
            float4* Bs4  = (float4*)Bs;
            float4* Ast4 = (float4*)Ast;

            for (int jt = 0; jt < 256; jt += 16) {
                #pragma unroll
                for (int r = 0; r < 4; r++) {
                    int q = tid + r * 256;
                    Bs4[q] = W2v[jt * 64 + q];
                }
                {
                    int q = tid;
                    float4 v = W1Tv[jt * 16 + q];
                    float aw = aas[jt + (q >> 4)];
                    v.x *= aw; v.y *= aw; v.z *= aw; v.w *= aw;
                    Ast4[q] = v;
                }
                __syncthreads();
                #pragma unroll
                for (int jj = 0; jj < 16; jj++) {
                    float4 a0 = Ast4[jj * 16 + tm * 2];
                    float4 a1 = Ast4[jj * 16 + tm * 2 + 1];
                    float4 b0 = Bs4[jj * 64 + tk * 2];
                    float4 b1 = Bs4[jj * 64 + tk * 2 + 1];
                    float am[8] = {a0.x, a0.y, a0.z, a0.w, a1.x, a1.y, a1.z, a1.w};
                    float bk[8] = {b0.x, b0.y, b0.z, b0.w, b1.x, b1.y, b1.z, b1.w};
                    #pragma unroll
                    for (int kk = 0; kk < 8; kk++)
                        #pragma unroll
                        for (int mm = 0; mm < 8; mm++)
                            acc[kk][mm] = fmaf(bk[kk], am[mm], acc[kk][mm]);
                }
                __syncthreads();
            }
            #pragma unroll
            for (int kk = 0; kk < 8; kk++) {
                int k = tk * 8 + kk;
                float4* dst = (float4*)(MsT + k * 68 + tm * 8);
                dst[0] = make_float4(acc[kk][0], acc[kk][1], acc[kk][2], acc[kk][3]);
                dst[1] = make_float4(acc[kk][4], acc[kk][5], acc[kk][6], acc[kk][7]);
            }
        }
        __syncthreads();

        // ---- Stage 6: H rows 32..63 += W1 diag(d) W1^T + M diag(e) M^T ----
        {
            const int kg = tid >> 6;   // 0..3 (k-split group)
            const int s  = tid & 63;
            const int si = s >> 3;     // i = si*4 .. +4   (H row = 32+i)
            const int sj = s & 7;      // j = sj*8 .. +8
            float acc2[4][8];
            #pragma unroll
            for (int i = 0; i < 4; i++)
                #pragma unroll
                for (int j = 0; j < 8; j++) acc2[i][j] = 0.0f;

            // H1: values from W1T tiles, weights = dds
            const float4* W1Tv = (const float4*)W1T;
            float4* Ast4 = (float4*)Ast;
            for (int kt = 0; kt < 256; kt += 16) {
                Ast4[tid] = W1Tv[kt * 16 + tid];
                __syncthreads();
                #pragma unroll
                for (int kq = 0; kq < 4; kq++) {
                    int kk = kg * 4 + kq;
                    float w  = dds[kt + kk];
                    float4 iv = Ast4[kk * 16 + 8 + si];
                    float4 j0 = Ast4[kk * 16 + sj * 2];
                    float4 j1 = Ast4[kk * 16 + sj * 2 + 1];
                    float ivw[4] = {iv.x * w, iv.y * w, iv.z * w, iv.w * w};
                    float jv[8]  = {j0.x, j0.y, j0.z, j0.w, j1.x, j1.y, j1.z, j1.w};
                    #pragma unroll
                    for (int ii = 0; ii < 4; ii++)
                        #pragma unroll
                        for (int jj = 0; jj < 8; jj++)
                            acc2[ii][jj] = fmaf(ivw[ii], jv[jj], acc2[ii][jj]);
                }
                __syncthreads();
            }
            // H2: values from MsT rows, weights = ees
            for (int k = kg; k < 256; k += 4) {
                const float4* Mr = (const float4*)(MsT + k * 68);
                float w  = ees[k];
                float4 iv = Mr[8 + si];
                float4 j0 = Mr[sj * 2];
                float4 j1 = Mr[sj * 2 + 1];
                float ivw[4] = {iv.x * w, iv.y * w, iv.z * w, iv.w * w};
                float jv[8]  = {j0.x, j0.y, j0.z, j0.w, j1.x, j1.y, j1.z, j1.w};
                #pragma unroll
                for (int ii = 0; ii < 4; ii++)
                    #pragma unroll
                    for (int jj = 0; jj < 8; jj++)
                        acc2[ii][jj] = fmaf(ivw[ii], jv[jj], acc2[ii][jj]);
            }
            #pragma unroll
            for (int ii = 0; ii < 4; ii++)
                #pragma unroll
                for (int jj = 0; jj < 8; jj++)
                    atomicAdd(&Hs[(si * 4 + ii) * 68 + sj * 8 + jj], acc2[ii][jj]);
        }
        __syncthreads();
    }

    // ---- Solve: (Hs[:,32:64] + 2I) qdd = g[:32] - Hs[:,0:32] qdot ----
    if (tid < 32) {
        int i = tid;
        float r = gsA[i];
        #pragma unroll 8
        for (int j = 0; j < 32; j++) r -= Hs[i * 68 + j] * xs[32 + j];
        #pragma unroll 8
        for (int j = 0; j < 32; j++)
            Sv[i * 34 + j] = Hs[i * 68 + 32 + j] + ((i == j) ? 2.0f : 0.0f);
        Sv[i * 34 + 32] = r;
    }
    __syncthreads();
    if (tid < 32) {
        int lane = tid;
        for (int p = 0; p < 32; p++) {
            // partial-pivot argmax over rows >= p
            float v = (lane >= p) ? fabsf(Sv[lane * 34 + p]) : -1.0f;
            int idx = lane;
            #pragma unroll
            for (int off = 16; off; off >>= 1) {
                float v2 = __shfl_xor_sync(0xffffffffu, v, off);
                int   i2 = __shfl_xor_sync(0xffffffffu, idx, off);
                if (v2 > v || (v2 == v && i2 < idx)) { v = v2; idx = i2; }
            }
            if (idx != p) {
                float t1 = Sv[p * 34 + lane];
                Sv[p * 34 + lane]   = Sv[idx * 34 + lane];
                Sv[idx * 34 + lane] = t1;
                if (lane == 0) {
                    float t2 = Sv[p * 34 + 32];
                    Sv[p * 34 + 32]   = Sv[idx * 34 + 32];
                    Sv[idx * 34 + 32] = t2;
                }
            }
            __syncwarp();
            float pinvv = 1.0f / Sv[p * 34 + p];
            if (lane != p) {
                float f = Sv[lane * 34 + p] * pinvv;
                for (int c = p; c < 33; c++)
                    Sv[lane * 34 + c] -= f * Sv[p * 34 + c];
            }
            __syncwarp();
        }
        float qdd = Sv[lane * 34 + 32] / Sv[lane * 34 + lane];
        out[b * 64 + lane]      = xs[32 + lane];
        out[b * 64 + 32 + lane] = qdd;
    }
}

extern "C" void kernel_launch(void* const* d_in, const int* in_sizes, int n_in,
                              void* d_out, int out_size)
{
    const float* x   = (const float*)d_in[0];
    const float* W1m = (const float*)d_in[1];
    const float* b1m = (const float*)d_in[2];
    const float* W2m = (const float*)d_in[3];
    const float* b2m = (const float*)d_in[4];
    const float* W3m = (const float*)d_in[5];
    const float* W1q = (const float*)d_in[6];
    const float* b1q = (const float*)d_in[7];
    const float* W2q = (const float*)d_in[8];
    const float* b2q = (const float*)d_in[9];
    const float* W3q = (const float*)d_in[10];
    float* out = (float*)d_out;

    int B = in_sizes[0] / 64;

    prep_kernel<<<256, 256>>>(W1m, W2m, W1q, W2q);
    cudaFuncSetAttribute(lnn_kernel, cudaFuncAttributeMaxDynamicSharedMemorySize, SMEM_BYTES);
    lnn_kernel<<<B, 256, SMEM_BYTES>>>(x, W1m, b1m, W2m, b2m, W3m,
                                       W1q, b1q, W2q, b2q, W3q, out);
}

// round 3
// speedup vs baseline: 1.0643x; 1.0643x over previous
#include <cuda_runtime.h>
#include <math.h>

#define HD 256
#define DD 64

// Prep scratch: transposed weights for coalesced access in the fused kernel.
__device__ float g_W1T[2 * DD * HD];   // [pass][(j*64 + m)]  (j hidden, m input)
__device__ float g_W2T[2 * HD * HD];   // [pass][(k*256 + j)]

__global__ void prep_kernel(const float* __restrict__ W1m, const float* __restrict__ W2m,
                            const float* __restrict__ W1q, const float* __restrict__ W2q)
{
    int t = blockIdx.x * blockDim.x + threadIdx.x;
    if (t < DD * HD) {
        int j = t >> 6, m = t & 63;
        g_W1T[t]           = W1m[m * HD + j];
        g_W1T[DD * HD + t] = W1q[m * HD + j];
    }
    if (t < HD * HD) {
        int k = t >> 8, j = t & 255;
        g_W2T[t]           = W2m[j * HD + k];
        g_W2T[HD * HD + t] = W2q[j * HD + k];
    }
}

// Shared memory layout (floats):
//   MsT   [256][68]   17408   M transposed (k-major), padded
//   Bs    [16][256]    4096   W2 j-tile for M GEMM; reused as reduction buffer in stage 6
//   Ast   [16][64]     1024   scaled W1T tile (also W1T tile in H1)
//   Hs    [32][68]     2176   Hessian rows 32..63 (accumulated over both MLPs)
//   h1s,aas,sss,ccs,ees,dds,aus : 7*256
//   xs[64], gsA[64], gpart[256], Sv[32*34]
#define SMEM_FLOATS (17408 + 4096 + 1024 + 2176 + 7*256 + 64 + 64 + 256 + 32*34)
#define SMEM_BYTES  (SMEM_FLOATS * 4)

__global__ __launch_bounds__(256, 2)
void lnn_kernel(const float* __restrict__ x,
                const float* __restrict__ W1m, const float* __restrict__ b1m,
                const float* __restrict__ W2m, const float* __restrict__ b2m,
                const float* __restrict__ W3m,
                const float* __restrict__ W1q, const float* __restrict__ b1q,
                const float* __restrict__ W2q, const float* __restrict__ b2q,
                const float* __restrict__ W3q,
                float* __restrict__ out)
{
    extern __shared__ float sm[];
    float* MsT   = sm;                 // 17408
    float* Bs    = MsT + 17408;        // 4096
    float* Ast   = Bs + 4096;          // 1024
    float* Hs    = Ast + 1024;         // 2176
    float* h1s   = Hs + 2176;          // 256
    float* aas   = h1s + 256;
    float* sss   = aas + 256;
    float* ccs   = sss + 256;
    float* ees   = ccs + 256;
    float* dds   = ees + 256;
    float* aus   = dds + 256;
    float* xs    = aus + 256;          // 64
    float* gsA   = xs + 64;            // 64
    float* gpart = gsA + 64;           // 256
    float* Sv    = gpart + 256;        // 1088

    const int tid = threadIdx.x;
    const int b   = blockIdx.x;

    for (int q = tid; q < 2176; q += 256) Hs[q] = 0.0f;
    if (tid < 64) { gsA[tid] = 0.0f; xs[tid] = x[b * 64 + tid]; }
    __syncthreads();

    #pragma unroll 1
    for (int pass = 0; pass < 2; pass++) {
        const float* W1  = pass ? W1q : W1m;
        const float* b1  = pass ? b1q : b1m;
        const float* W2  = pass ? W2q : W2m;
        const float* b2  = pass ? b2q : b2m;
        const float* W3  = pass ? W3q : W3m;
        const float* W1T = g_W1T + pass * (DD * HD);
        const float* W2T = g_W2T + pass * (HD * HD);

        // ---- Stage 1: z1 = x W1 + b1 ; h1, a = act', s = act'' ----
        {
            int j = tid;
            float z = b1[j];
            const float4* xv = (const float4*)xs;
            #pragma unroll 4
            for (int i4 = 0; i4 < 16; i4++) {
                float4 v = xv[i4];
                int i = i4 * 4;
                z = fmaf(v.x, W1[(i + 0) * HD + j], z);
                z = fmaf(v.y, W1[(i + 1) * HD + j], z);
                z = fmaf(v.z, W1[(i + 2) * HD + j], z);
                z = fmaf(v.w, W1[(i + 3) * HD + j], z);
            }
            float h, a, s;
            if (pass == 0) {
                float sg = 1.0f / (1.0f + __expf(-z));
                h = fmaxf(z, 0.0f) + log1pf(__expf(-fabsf(z)));
                a = sg;
                s = sg * (1.0f - sg);
            } else {
                float t = tanhf(0.5f * z);
                float o = 1.0f - t * t;
                h = z * t;
                a = fmaf(0.5f * z, o, t);
                s = o * (1.0f - 0.5f * z * t);
            }
            h1s[j] = h; aas[j] = a; sss[j] = s;
        }
        __syncthreads();

        // ---- Stage 2: z2 = h1 W2 + b2 ; c = act'(z2)*w3, e = act''(z2)*w3 ----
        {
            int k = tid;
            float z = b2[k];
            const float4* hv4 = (const float4*)h1s;
            #pragma unroll 4
            for (int l4 = 0; l4 < 64; l4++) {
                float4 v = hv4[l4];
                int l = l4 * 4;
                z = fmaf(v.x, W2[(l + 0) * HD + k], z);
                z = fmaf(v.y, W2[(l + 1) * HD + k], z);
                z = fmaf(v.z, W2[(l + 2) * HD + k], z);
                z = fmaf(v.w, W2[(l + 3) * HD + k], z);
            }
            float a, s;
            if (pass == 0) {
                float sg = 1.0f / (1.0f + __expf(-z));
                a = sg;
                s = sg * (1.0f - sg);
            } else {
                float t = tanhf(0.5f * z);
                float o = 1.0f - t * t;
                a = fmaf(0.5f * z, o, t);
                s = o * (1.0f - 0.5f * z * t);
            }
            float w3v = W3[k];
            ccs[k] = a * w3v;
            ees[k] = s * w3v;
        }
        __syncthreads();

        // ---- Stage 3: u = W2 c ; d = s*u, au = a*u ----
        {
            int j = tid;
            float u = 0.0f;
            const float4* cv4 = (const float4*)ccs;
            #pragma unroll 4
            for (int k4 = 0; k4 < 64; k4++) {
                float4 v = cv4[k4];
                int k = k4 * 4;
                u = fmaf(v.x, W2T[(k + 0) * HD + j], u);
                u = fmaf(v.y, W2T[(k + 1) * HD + j], u);
                u = fmaf(v.z, W2T[(k + 2) * HD + j], u);
                u = fmaf(v.w, W2T[(k + 3) * HD + j], u);
            }
            dds[j] = sss[j] * u;
            aus[j] = aas[j] * u;
        }
        __syncthreads();

        // ---- Stage 4: gradient g = W1 (a*u), 4-way j-split ----
        {
            int m = tid & 63, part = tid >> 6;
            const float* W1Tp = W1T + part * 64 * 64;
            const float4* av4 = (const float4*)(aus + part * 64);
            float gp = 0.0f;
            #pragma unroll 4
            for (int j4 = 0; j4 < 16; j4++) {
                float4 v = av4[j4];
                int jj = j4 * 4;
                gp = fmaf(W1Tp[(jj + 0) * 64 + m], v.x, gp);
                gp = fmaf(W1Tp[(jj + 1) * 64 + m], v.y, gp);
                gp = fmaf(W1Tp[(jj + 2) * 64 + m], v.z, gp);
                gp = fmaf(W1Tp[(jj + 3) * 64 + m], v.w, gp);
            }
            gpart[part * 64 + m] = gp;
        }
        __syncthreads();
        if (tid < 64)
            gsA[tid] += gpart[tid] + gpart[64 + tid] + gpart[128 + tid] + gpart[192 + tid];

        // ---- Stage 5: M = (W1 . a) W2  ->  MsT[k][m] (k-major) ----
        {
            const int tk = tid >> 3;   // 0..31 -> k tile *8
            const int tm = tid & 7;    // 0..7  -> m tile *8
            float acc[8][8];
            #pragma unroll
            for (int i = 0; i < 8; i++)
                #pragma unroll
                for (int j = 0; j < 8; j++) acc[i][j] = 0.0f;

            const float4* W2v  = (const float4*)W2;
            const float4* W1Tv = (const float4*)W1T;
            float4* Bs4  = (float4*)Bs;
            float4* Ast4 = (float4*)Ast;

            for (int jt = 0; jt < 256; jt += 16) {
                #pragma unroll
                for (int r = 0; r < 4; r++) {
                    int q = tid + r * 256;
                    Bs4[q] = W2v[jt * 64 + q];
                }
                {
                    int q = tid;
                    float4 v = W1Tv[jt * 16 + q];
                    float aw = aas[jt + (q >> 4)];
                    v.x *= aw; v.y *= aw; v.z *= aw; v.w *= aw;
                    Ast4[q] = v;
                }
                __syncthreads();
                #pragma unroll
                for (int jj = 0; jj < 16; jj++) {
                    float4 a0 = Ast4[jj * 16 + tm * 2];
                    float4 a1 = Ast4[jj * 16 + tm * 2 + 1];
                    float4 b0 = Bs4[jj * 64 + tk * 2];
                    float4 b1 = Bs4[jj * 64 + tk * 2 + 1];
                    float am[8] = {a0.x, a0.y, a0.z, a0.w, a1.x, a1.y, a1.z, a1.w};
                    float bk[8] = {b0.x, b0.y, b0.z, b0.w, b1.x, b1.y, b1.z, b1.w};
                    #pragma unroll
                    for (int kk = 0; kk < 8; kk++)
                        #pragma unroll
                        for (int mm = 0; mm < 8; mm++)
                            acc[kk][mm] = fmaf(bk[kk], am[mm], acc[kk][mm]);
                }
                __syncthreads();
            }
            #pragma unroll
            for (int kk = 0; kk < 8; kk++) {
                int k = tk * 8 + kk;
                float4* dst = (float4*)(MsT + k * 68 + tm * 8);
                dst[0] = make_float4(acc[kk][0], acc[kk][1], acc[kk][2], acc[kk][3]);
                dst[1] = make_float4(acc[kk][4], acc[kk][5], acc[kk][6], acc[kk][7]);
            }
        }
        __syncthreads();

        // ---- Stage 6: H rows 32..63 += W1 diag(d) W1^T + M diag(e) M^T ----
        {
            const int kg = tid >> 6;   // 0..3 (k-split group; warp-pair granular)
            const int s  = tid & 63;
            const int si = s >> 3;     // i = si*4 .. +4   (H row = 32+i)
            const int sj = s & 7;      // j = sj*8 .. +8
            float acc2[4][8];
            #pragma unroll
            for (int i = 0; i < 4; i++)
                #pragma unroll
                for (int j = 0; j < 8; j++) acc2[i][j] = 0.0f;

            // H1: values from W1T tiles, weights = dds
            const float4* W1Tv = (const float4*)W1T;
            float4* Ast4 = (float4*)Ast;
            for (int kt = 0; kt < 256; kt += 16) {
                Ast4[tid] = W1Tv[kt * 16 + tid];
                __syncthreads();
                #pragma unroll
                for (int kq = 0; kq < 4; kq++) {
                    int kk = kg * 4 + kq;
                    float w  = dds[kt + kk];
                    float4 iv = Ast4[kk * 16 + 8 + si];
                    float4 j0 = Ast4[kk * 16 + sj * 2];
                    float4 j1 = Ast4[kk * 16 + sj * 2 + 1];
                    float ivw[4] = {iv.x * w, iv.y * w, iv.z * w, iv.w * w};
                    float jv[8]  = {j0.x, j0.y, j0.z, j0.w, j1.x, j1.y, j1.z, j1.w};
                    #pragma unroll
                    for (int ii = 0; ii < 4; ii++)
                        #pragma unroll
                        for (int jj = 0; jj < 8; jj++)
                            acc2[ii][jj] = fmaf(ivw[ii], jv[jj], acc2[ii][jj]);
                }
                __syncthreads();
            }
            // H2: values from MsT rows, weights = ees
            for (int k = kg; k < 256; k += 4) {
                const float4* Mr = (const float4*)(MsT + k * 68);
                float w  = ees[k];
                float4 iv = Mr[8 + si];
                float4 j0 = Mr[sj * 2];
                float4 j1 = Mr[sj * 2 + 1];
                float ivw[4] = {iv.x * w, iv.y * w, iv.z * w, iv.w * w};
                float jv[8]  = {j0.x, j0.y, j0.z, j0.w, j1.x, j1.y, j1.z, j1.w};
                #pragma unroll
                for (int ii = 0; ii < 4; ii++)
                    #pragma unroll
                    for (int jj = 0; jj < 8; jj++)
                        acc2[ii][jj] = fmaf(ivw[ii], jv[jj], acc2[ii][jj]);
            }

            // ---- staged tree reduction over the 4 k-groups (no atomics) ----
            // Bs (4096 floats) is free here. Layout: [half][s][32].
            {
                float4* red4 = (float4*)Bs;
                // step 1: groups 1 and 3 stage their accumulators
                if (kg & 1) {
                    float4* dst = red4 + ((kg >> 1) ? 512 : 0) + s * 8;
                    #pragma unroll
                    for (int ii = 0; ii < 4; ii++) {
                        dst[ii * 2 + 0] = make_float4(acc2[ii][0], acc2[ii][1], acc2[ii][2], acc2[ii][3]);
                        dst[ii * 2 + 1] = make_float4(acc2[ii][4], acc2[ii][5], acc2[ii][6], acc2[ii][7]);
                    }
                }
                __syncthreads();
                // step 2: groups 0 and 2 absorb
                if (!(kg & 1)) {
                    const float4* src = red4 + ((kg >> 1) ? 512 : 0) + s * 8;
                    #pragma unroll
                    for (int ii = 0; ii < 4; ii++) {
                        float4 v0 = src[ii * 2 + 0], v1 = src[ii * 2 + 1];
                        acc2[ii][0] += v0.x; acc2[ii][1] += v0.y; acc2[ii][2] += v0.z; acc2[ii][3] += v0.w;
                        acc2[ii][4] += v1.x; acc2[ii][5] += v1.y; acc2[ii][6] += v1.z; acc2[ii][7] += v1.w;
                    }
                }
                __syncthreads();
                // step 3: group 2 stages its partial sum
                if (kg == 2) {
                    float4* dst = red4 + s * 8;
                    #pragma unroll
                    for (int ii = 0; ii < 4; ii++) {
                        dst[ii * 2 + 0] = make_float4(acc2[ii][0], acc2[ii][1], acc2[ii][2], acc2[ii][3]);
                        dst[ii * 2 + 1] = make_float4(acc2[ii][4], acc2[ii][5], acc2[ii][6], acc2[ii][7]);
                    }
                }
                __syncthreads();
                // step 4: group 0 finishes and commits to Hs (single writer)
                if (kg == 0) {
                    const float4* src = red4 + s * 8;
                    #pragma unroll
                    for (int ii = 0; ii < 4; ii++) {
                        float4 v0 = src[ii * 2 + 0], v1 = src[ii * 2 + 1];
                        acc2[ii][0] += v0.x; acc2[ii][1] += v0.y; acc2[ii][2] += v0.z; acc2[ii][3] += v0.w;
                        acc2[ii][4] += v1.x; acc2[ii][5] += v1.y; acc2[ii][6] += v1.z; acc2[ii][7] += v1.w;
                        float4* hrow = (float4*)(Hs + (si * 4 + ii) * 68 + sj * 8);
                        float4 h0 = hrow[0], h1v = hrow[1];
                        hrow[0] = make_float4(h0.x + acc2[ii][0], h0.y + acc2[ii][1],
                                              h0.z + acc2[ii][2], h0.w + acc2[ii][3]);
                        hrow[1] = make_float4(h1v.x + acc2[ii][4], h1v.y + acc2[ii][5],
                                              h1v.z + acc2[ii][6], h1v.w + acc2[ii][7]);
                    }
                }
            }
        }
        __syncthreads();
    }

    // ---- Solve: (Hs[:,32:64] + 2I) qdd = g[:32] - Hs[:,0:32] qdot ----
    if (tid < 32) {
        int i = tid;
        float r = gsA[i];
        #pragma unroll 8
        for (int j = 0; j < 32; j++) r -= Hs[i * 68 + j] * xs[32 + j];
        #pragma unroll 8
        for (int j = 0; j < 32; j++)
            Sv[i * 34 + j] = Hs[i * 68 + 32 + j] + ((i == j) ? 2.0f : 0.0f);
        Sv[i * 34 + 32] = r;
    }
    __syncthreads();
    if (tid < 32) {
        int lane = tid;
        for (int p = 0; p < 32; p++) {
            // partial-pivot argmax over rows >= p
            float v = (lane >= p) ? fabsf(Sv[lane * 34 + p]) : -1.0f;
            int idx = lane;
            #pragma unroll
            for (int off = 16; off; off >>= 1) {
                float v2 = __shfl_xor_sync(0xffffffffu, v, off);
                int   i2 = __shfl_xor_sync(0xffffffffu, idx, off);
                if (v2 > v || (v2 == v && i2 < idx)) { v = v2; idx = i2; }
            }
            if (idx != p) {
                float t1 = Sv[p * 34 + lane];
                Sv[p * 34 + lane]   = Sv[idx * 34 + lane];
                Sv[idx * 34 + lane] = t1;
                if (lane == 0) {
                    float t2 = Sv[p * 34 + 32];
                    Sv[p * 34 + 32]   = Sv[idx * 34 + 32];
                    Sv[idx * 34 + 32] = t2;
                }
            }
            __syncwarp();
            float pinvv = 1.0f / Sv[p * 34 + p];
            if (lane != p) {
                float f = Sv[lane * 34 + p] * pinvv;
                for (int c = p; c < 33; c++)
                    Sv[lane * 34 + c] -= f * Sv[p * 34 + c];
            }
            __syncwarp();
        }
        float qdd = Sv[lane * 34 + 32] / Sv[lane * 34 + lane];
        out[b * 64 + lane]      = xs[32 + lane];
        out[b * 64 + 32 + lane] = qdd;
    }
}

extern "C" void kernel_launch(void* const* d_in, const int* in_sizes, int n_in,
                              void* d_out, int out_size)
{
    const float* x   = (const float*)d_in[0];
    const float* W1m = (const float*)d_in[1];
    const float* b1m = (const float*)d_in[2];
    const float* W2m = (const float*)d_in[3];
    const float* b2m = (const float*)d_in[4];
    const float* W3m = (const float*)d_in[5];
    const float* W1q = (const float*)d_in[6];
    const float* b1q = (const float*)d_in[7];
    const float* W2q = (const float*)d_in[8];
    const float* b2q = (const float*)d_in[9];
    const float* W3q = (const float*)d_in[10];
    float* out = (float*)d_out;

    int B = in_sizes[0] / 64;

    prep_kernel<<<256, 256>>>(W1m, W2m, W1q, W2q);
    cudaFuncSetAttribute(lnn_kernel, cudaFuncAttributeMaxDynamicSharedMemorySize, SMEM_BYTES);
    lnn_kernel<<<B, 256, SMEM_BYTES>>>(x, W1m, b1m, W2m, b2m, W3m,
                                       W1q, b1q, W2q, b2q, W3q, out);
}

// round 4
// speedup vs baseline: 1.0646x; 1.0004x over previous
#include <cuda_runtime.h>
#include <math.h>

#define HD 256
#define DD 64

// Prep scratch: transposed weights for coalesced access in the fused kernel.
__device__ float g_W1T[2 * DD * HD];   // [pass][(j*64 + m)]  (j hidden, m input)
__device__ float g_W2T[2 * HD * HD];   // [pass][(k*256 + j)]

__global__ void prep_kernel(const float* __restrict__ W1m, const float* __restrict__ W2m,
                            const float* __restrict__ W1q, const float* __restrict__ W2q)
{
    int t = blockIdx.x * blockDim.x + threadIdx.x;
    if (t < DD * HD) {
        int j = t >> 6, m = t & 63;
        g_W1T[t]           = W1m[m * HD + j];
        g_W1T[DD * HD + t] = W1q[m * HD + j];
    }
    if (t < HD * HD) {
        int k = t >> 8, j = t & 255;
        g_W2T[t]           = W2m[j * HD + k];
        g_W2T[HD * HD + t] = W2q[j * HD + k];
    }
}

// Shared memory layout (floats):
//   MsT   [256][68]   17408   M transposed (k-major), padded
//   Bs    [16][256]    4096   W2 j-tile for M GEMM; reused as reduction buffer in stage 6
//   Ast   [16][64]     1024   scaled W1T tile (also W1T tile in H1)
//   Hs    [32][68]     2176   Hessian rows 32..63 (accumulated over both MLPs)
//   h1s,aas,sss,ccs,ees,dds,aus : 7*256
//   xs[64], gsA[64], gpart[256], Sv[32*34]
#define SMEM_FLOATS (17408 + 4096 + 1024 + 2176 + 7*256 + 64 + 64 + 256 + 32*34)
#define SMEM_BYTES  (SMEM_FLOATS * 4)

__global__ __launch_bounds__(256, 2)
void lnn_kernel(const float* __restrict__ x,
                const float* __restrict__ W1m, const float* __restrict__ b1m,
                const float* __restrict__ W2m, const float* __restrict__ b2m,
                const float* __restrict__ W3m,
                const float* __restrict__ W1q, const float* __restrict__ b1q,
                const float* __restrict__ W2q, const float* __restrict__ b2q,
                const float* __restrict__ W3q,
                float* __restrict__ out)
{
    extern __shared__ float sm[];
    float* MsT   = sm;                 // 17408
    float* Bs    = MsT + 17408;        // 4096
    float* Ast   = Bs + 4096;          // 1024
    float* Hs    = Ast + 1024;         // 2176
    float* h1s   = Hs + 2176;          // 256
    float* aas   = h1s + 256;
    float* sss   = aas + 256;
    float* ccs   = sss + 256;
    float* ees   = ccs + 256;
    float* dds   = ees + 256;
    float* aus   = dds + 256;
    float* xs    = aus + 256;          // 64
    float* gsA   = xs + 64;            // 64
    float* gpart = gsA + 64;           // 256
    float* Sv    = gpart + 256;        // 1088

    const int tid = threadIdx.x;
    const int b   = blockIdx.x;

    for (int q = tid; q < 2176; q += 256) Hs[q] = 0.0f;
    if (tid < 64) { gsA[tid] = 0.0f; xs[tid] = x[b * 64 + tid]; }
    __syncthreads();

    #pragma unroll 1
    for (int pass = 0; pass < 2; pass++) {
        const float* W1  = pass ? W1q : W1m;
        const float* b1  = pass ? b1q : b1m;
        const float* W2  = pass ? W2q : W2m;
        const float* b2  = pass ? b2q : b2m;
        const float* W3  = pass ? W3q : W3m;
        const float* W1T = g_W1T + pass * (DD * HD);
        const float* W2T = g_W2T + pass * (HD * HD);

        // ---- Stage 1: z1 = x W1 + b1 ; h1, a = act', s = act'' ----
        {
            int j = tid;
            float z = b1[j];
            const float4* xv = (const float4*)xs;
            #pragma unroll 4
            for (int i4 = 0; i4 < 16; i4++) {
                float4 v = xv[i4];
                int i = i4 * 4;
                z = fmaf(v.x, W1[(i + 0) * HD + j], z);
                z = fmaf(v.y, W1[(i + 1) * HD + j], z);
                z = fmaf(v.z, W1[(i + 2) * HD + j], z);
                z = fmaf(v.w, W1[(i + 3) * HD + j], z);
            }
            float h, a, s;
            if (pass == 0) {
                float sg = 1.0f / (1.0f + __expf(-z));
                h = fmaxf(z, 0.0f) + log1pf(__expf(-fabsf(z)));
                a = sg;
                s = sg * (1.0f - sg);
            } else {
                float t = tanhf(0.5f * z);
                float o = 1.0f - t * t;
                h = z * t;
                a = fmaf(0.5f * z, o, t);
                s = o * (1.0f - 0.5f * z * t);
            }
            h1s[j] = h; aas[j] = a; sss[j] = s;
        }
        __syncthreads();

        // ---- Stage 2: z2 = h1 W2 + b2 ; c = act'(z2)*w3, e = act''(z2)*w3 ----
        {
            int k = tid;
            float z = b2[k];
            const float4* hv4 = (const float4*)h1s;
            #pragma unroll 4
            for (int l4 = 0; l4 < 64; l4++) {
                float4 v = hv4[l4];
                int l = l4 * 4;
                z = fmaf(v.x, W2[(l + 0) * HD + k], z);
                z = fmaf(v.y, W2[(l + 1) * HD + k], z);
                z = fmaf(v.z, W2[(l + 2) * HD + k], z);
                z = fmaf(v.w, W2[(l + 3) * HD + k], z);
            }
            float a, s;
            if (pass == 0) {
                float sg = 1.0f / (1.0f + __expf(-z));
                a = sg;
                s = sg * (1.0f - sg);
            } else {
                float t = tanhf(0.5f * z);
                float o = 1.0f - t * t;
                a = fmaf(0.5f * z, o, t);
                s = o * (1.0f - 0.5f * z * t);
            }
            float w3v = W3[k];
            ccs[k] = a * w3v;
            ees[k] = s * w3v;
        }
        __syncthreads();

        // ---- Stage 3: u = W2 c ; d = s*u, au = a*u ----
        {
            int j = tid;
            float u = 0.0f;
            const float4* cv4 = (const float4*)ccs;
            #pragma unroll 4
            for (int k4 = 0; k4 < 64; k4++) {
                float4 v = cv4[k4];
                int k = k4 * 4;
                u = fmaf(v.x, W2T[(k + 0) * HD + j], u);
                u = fmaf(v.y, W2T[(k + 1) * HD + j], u);
                u = fmaf(v.z, W2T[(k + 2) * HD + j], u);
                u = fmaf(v.w, W2T[(k + 3) * HD + j], u);
            }
            dds[j] = sss[j] * u;
            aus[j] = aas[j] * u;
        }
        __syncthreads();

        // ---- Stage 4: gradient g = W1 (a*u), 4-way j-split ----
        {
            int m = tid & 63, part = tid >> 6;
            const float* W1Tp = W1T + part * 64 * 64;
            const float4* av4 = (const float4*)(aus + part * 64);
            float gp = 0.0f;
            #pragma unroll 4
            for (int j4 = 0; j4 < 16; j4++) {
                float4 v = av4[j4];
                int jj = j4 * 4;
                gp = fmaf(W1Tp[(jj + 0) * 64 + m], v.x, gp);
                gp = fmaf(W1Tp[(jj + 1) * 64 + m], v.y, gp);
                gp = fmaf(W1Tp[(jj + 2) * 64 + m], v.z, gp);
                gp = fmaf(W1Tp[(jj + 3) * 64 + m], v.w, gp);
            }
            gpart[part * 64 + m] = gp;
        }
        __syncthreads();
        if (tid < 64)
            gsA[tid] += gpart[tid] + gpart[64 + tid] + gpart[128 + tid] + gpart[192 + tid];

        // ---- Stage 5: M = (W1 . a) W2  ->  MsT[k][m] (k-major) ----
        {
            const int tk = tid >> 3;   // 0..31 -> k tile *8
            const int tm = tid & 7;    // 0..7  -> m tile *8
            float acc[8][8];
            #pragma unroll
            for (int i = 0; i < 8; i++)
                #pragma unroll
                for (int j = 0; j < 8; j++) acc[i][j] = 0.0f;

            const float4* W2v  = (const float4*)W2;
            const float4* W1Tv = (const float4*)W1T;
            float4* Bs4  = (float4*)Bs;
            float4* Ast4 = (float4*)Ast;

            for (int jt = 0; jt < 256; jt += 16) {
                #pragma unroll
                for (int r = 0; r < 4; r++) {
                    int q = tid + r * 256;
                    Bs4[q] = W2v[jt * 64 + q];
                }
                {
                    int q = tid;
                    float4 v = W1Tv[jt * 16 + q];
                    float aw = aas[jt + (q >> 4)];
                    v.x *= aw; v.y *= aw; v.z *= aw; v.w *= aw;
                    Ast4[q] = v;
                }
                __syncthreads();
                #pragma unroll
                for (int jj = 0; jj < 16; jj++) {
                    float4 a0 = Ast4[jj * 16 + tm * 2];
                    float4 a1 = Ast4[jj * 16 + tm * 2 + 1];
                    float4 b0 = Bs4[jj * 64 + tk * 2];
                    float4 b1 = Bs4[jj * 64 + tk * 2 + 1];
                    float am[8] = {a0.x, a0.y, a0.z, a0.w, a1.x, a1.y, a1.z, a1.w};
                    float bk[8] = {b0.x, b0.y, b0.z, b0.w, b1.x, b1.y, b1.z, b1.w};
                    #pragma unroll
                    for (int kk = 0; kk < 8; kk++)
                        #pragma unroll
                        for (int mm = 0; mm < 8; mm++)
                            acc[kk][mm] = fmaf(bk[kk], am[mm], acc[kk][mm]);
                }
                __syncthreads();
            }
            #pragma unroll
            for (int kk = 0; kk < 8; kk++) {
                int k = tk * 8 + kk;
                float4* dst = (float4*)(MsT + k * 68 + tm * 8);
                dst[0] = make_float4(acc[kk][0], acc[kk][1], acc[kk][2], acc[kk][3]);
                dst[1] = make_float4(acc[kk][4], acc[kk][5], acc[kk][6], acc[kk][7]);
            }
        }
        __syncthreads();

        // ---- Stage 6: H rows 32..63 += W1 diag(d) W1^T + M diag(e) M^T ----
        {
            const int kg = tid >> 6;   // 0..3 (k-split group; warp-pair granular)
            const int s  = tid & 63;
            const int si = s >> 3;     // i = si*4 .. +4   (H row = 32+i)
            const int sj = s & 7;      // j = sj*8 .. +8
            float acc2[4][8];
            #pragma unroll
            for (int i = 0; i < 4; i++)
                #pragma unroll
                for (int j = 0; j < 8; j++) acc2[i][j] = 0.0f;

            // H1: values from W1T tiles, weights = dds
            const float4* W1Tv = (const float4*)W1T;
            float4* Ast4 = (float4*)Ast;
            for (int kt = 0; kt < 256; kt += 16) {
                Ast4[tid] = W1Tv[kt * 16 + tid];
                __syncthreads();
                #pragma unroll
                for (int kq = 0; kq < 4; kq++) {
                    int kk = kg * 4 + kq;
                    float w  = dds[kt + kk];
                    float4 iv = Ast4[kk * 16 + 8 + si];
                    float4 j0 = Ast4[kk * 16 + sj * 2];
                    float4 j1 = Ast4[kk * 16 + sj * 2 + 1];
                    float ivw[4] = {iv.x * w, iv.y * w, iv.z * w, iv.w * w};
                    float jv[8]  = {j0.x, j0.y, j0.z, j0.w, j1.x, j1.y, j1.z, j1.w};
                    #pragma unroll
                    for (int ii = 0; ii < 4; ii++)
                        #pragma unroll
                        for (int jj = 0; jj < 8; jj++)
                            acc2[ii][jj] = fmaf(ivw[ii], jv[jj], acc2[ii][jj]);
                }
                __syncthreads();
            }
            // H2: values from MsT rows, weights = ees
            for (int k = kg; k < 256; k += 4) {
                const float4* Mr = (const float4*)(MsT + k * 68);
                float w  = ees[k];
                float4 iv = Mr[8 + si];
                float4 j0 = Mr[sj * 2];
                float4 j1 = Mr[sj * 2 + 1];
                float ivw[4] = {iv.x * w, iv.y * w, iv.z * w, iv.w * w};
                float jv[8]  = {j0.x, j0.y, j0.z, j0.w, j1.x, j1.y, j1.z, j1.w};
                #pragma unroll
                for (int ii = 0; ii < 4; ii++)
                    #pragma unroll
                    for (int jj = 0; jj < 8; jj++)
                        acc2[ii][jj] = fmaf(ivw[ii], jv[jj], acc2[ii][jj]);
            }

            // ---- staged tree reduction over the 4 k-groups (no atomics) ----
            // Bs (4096 floats) is free here. Layout: [half][s][32].
            {
                float4* red4 = (float4*)Bs;
                // step 1: groups 1 and 3 stage their accumulators
                if (kg & 1) {
                    float4* dst = red4 + ((kg >> 1) ? 512 : 0) + s * 8;
                    #pragma unroll
                    for (int ii = 0; ii < 4; ii++) {
                        dst[ii * 2 + 0] = make_float4(acc2[ii][0], acc2[ii][1], acc2[ii][2], acc2[ii][3]);
                        dst[ii * 2 + 1] = make_float4(acc2[ii][4], acc2[ii][5], acc2[ii][6], acc2[ii][7]);
                    }
                }
                __syncthreads();
                // step 2: groups 0 and 2 absorb
                if (!(kg & 1)) {
                    const float4* src = red4 + ((kg >> 1) ? 512 : 0) + s * 8;
                    #pragma unroll
                    for (int ii = 0; ii < 4; ii++) {
                        float4 v0 = src[ii * 2 + 0], v1 = src[ii * 2 + 1];
                        acc2[ii][0] += v0.x; acc2[ii][1] += v0.y; acc2[ii][2] += v0.z; acc2[ii][3] += v0.w;
                        acc2[ii][4] += v1.x; acc2[ii][5] += v1.y; acc2[ii][6] += v1.z; acc2[ii][7] += v1.w;
                    }
                }
                __syncthreads();
                // step 3: group 2 stages its partial sum
                if (kg == 2) {
                    float4* dst = red4 + s * 8;
                    #pragma unroll
                    for (int ii = 0; ii < 4; ii++) {
                        dst[ii * 2 + 0] = make_float4(acc2[ii][0], acc2[ii][1], acc2[ii][2], acc2[ii][3]);
                        dst[ii * 2 + 1] = make_float4(acc2[ii][4], acc2[ii][5], acc2[ii][6], acc2[ii][7]);
                    }
                }
                __syncthreads();
                // step 4: group 0 finishes and commits to Hs (single writer)
                if (kg == 0) {
                    const float4* src = red4 + s * 8;
                    #pragma unroll
                    for (int ii = 0; ii < 4; ii++) {
                        float4 v0 = src[ii * 2 + 0], v1 = src[ii * 2 + 1];
                        acc2[ii][0] += v0.x; acc2[ii][1] += v0.y; acc2[ii][2] += v0.z; acc2[ii][3] += v0.w;
                        acc2[ii][4] += v1.x; acc2[ii][5] += v1.y; acc2[ii][6] += v1.z; acc2[ii][7] += v1.w;
                        float4* hrow = (float4*)(Hs + (si * 4 + ii) * 68 + sj * 8);
                        float4 h0 = hrow[0], h1v = hrow[1];
                        hrow[0] = make_float4(h0.x + acc2[ii][0], h0.y + acc2[ii][1],
                                              h0.z + acc2[ii][2], h0.w + acc2[ii][3]);
                        hrow[1] = make_float4(h1v.x + acc2[ii][4], h1v.y + acc2[ii][5],
                                              h1v.z + acc2[ii][6], h1v.w + acc2[ii][7]);
                    }
                }
            }
        }
        __syncthreads();
    }

    // ---- Solve: (Hs[:,32:64] + 2I) qdd = g[:32] - Hs[:,0:32] qdot ----
    if (tid < 32) {
        int i = tid;
        float r = gsA[i];
        #pragma unroll 8
        for (int j = 0; j < 32; j++) r -= Hs[i * 68 + j] * xs[32 + j];
        #pragma unroll 8
        for (int j = 0; j < 32; j++)
            Sv[i * 34 + j] = Hs[i * 68 + 32 + j] + ((i == j) ? 2.0f : 0.0f);
        Sv[i * 34 + 32] = r;
    }
    __syncthreads();
    if (tid < 32) {
        int lane = tid;
        for (int p = 0; p < 32; p++) {
            // partial-pivot argmax over rows >= p
            float v = (lane >= p) ? fabsf(Sv[lane * 34 + p]) : -1.0f;
            int idx = lane;
            #pragma unroll
            for (int off = 16; off; off >>= 1) {
                float v2 = __shfl_xor_sync(0xffffffffu, v, off);
                int   i2 = __shfl_xor_sync(0xffffffffu, idx, off);
                if (v2 > v || (v2 == v && i2 < idx)) { v = v2; idx = i2; }
            }
            if (idx != p) {
                float t1 = Sv[p * 34 + lane];
                Sv[p * 34 + lane]   = Sv[idx * 34 + lane];
                Sv[idx * 34 + lane] = t1;
                if (lane == 0) {
                    float t2 = Sv[p * 34 + 32];
                    Sv[p * 34 + 32]   = Sv[idx * 34 + 32];
                    Sv[idx * 34 + 32] = t2;
                }
            }
            __syncwarp();
            float pinvv = 1.0f / Sv[p * 34 + p];
            if (lane != p) {
                float f = Sv[lane * 34 + p] * pinvv;
                for (int c = p; c < 33; c++)
                    Sv[lane * 34 + c] -= f * Sv[p * 34 + c];
            }
            __syncwarp();
        }
        float qdd = Sv[lane * 34 + 32] / Sv[lane * 34 + lane];
        out[b * 64 + lane]      = xs[32 + lane];
        out[b * 64 + 32 + lane] = qdd;
    }
}

extern "C" void kernel_launch(void* const* d_in, const int* in_sizes, int n_in,
                              void* d_out, int out_size)
{
    const float* x   = (const float*)d_in[0];
    const float* W1m = (const float*)d_in[1];
    const float* b1m = (const float*)d_in[2];
    const float* W2m = (const float*)d_in[3];
    const float* b2m = (const float*)d_in[4];
    const float* W3m = (const float*)d_in[5];
    const float* W1q = (const float*)d_in[6];
    const float* b1q = (const float*)d_in[7];
    const float* W2q = (const float*)d_in[8];
    const float* b2q = (const float*)d_in[9];
    const float* W3q = (const float*)d_in[10];
    float* out = (float*)d_out;

    int B = in_sizes[0] / 64;

    prep_kernel<<<256, 256>>>(W1m, W2m, W1q, W2q);
    cudaFuncSetAttribute(lnn_kernel, cudaFuncAttributeMaxDynamicSharedMemorySize, SMEM_BYTES);
    lnn_kernel<<<B, 256, SMEM_BYTES>>>(x, W1m, b1m, W2m, b2m, W3m,
                                       W1q, b1q, W2q, b2q, W3q, out);
}

// round 5
// speedup vs baseline: 1.1849x; 1.1130x over previous
#include <cuda_runtime.h>
#include <math.h>

#define HD 256
#define DD 64

// Prep scratch: transposed weights for coalesced access in the fused kernel.
__device__ float g_W1T[2 * DD * HD];   // [pass][(j*64 + m)]
__device__ float g_W2T[2 * HD * HD];   // [pass][(k*256 + j)]

__global__ void prep_kernel(const float* __restrict__ W1m, const float* __restrict__ W2m,
                            const float* __restrict__ W1q, const float* __restrict__ W2q)
{
    int t = blockIdx.x * blockDim.x + threadIdx.x;
    if (t < DD * HD) {
        int j = t >> 6, m = t & 63;
        g_W1T[t]           = W1m[m * HD + j];
        g_W1T[DD * HD + t] = W1q[m * HD + j];
    }
    if (t < HD * HD) {
        int k = t >> 8, j = t & 255;
        g_W2T[t]           = W2m[j * HD + k];
        g_W2T[HD * HD + t] = W2q[j * HD + k];
    }
}

// Shared memory layout (floats):
//   Mt    [128][68]    8704   M k-tile (k-major), padded; reused as nothing else
//   Bs    [16][128]    2048   W2 j-tile for GEMM; reused as reduction buffer
//   Ast   [16][64]     1024   scaled W1T tile / W1T tile in H1
//   Hs    [32][68]     2176
//   h1s,aas,sss,ccs,ees,dds,aus : 7*256 = 1792
//   xs[64], gsA[64], gpart[256], Sv[32*34]
#define SMEM_FLOATS (8704 + 2048 + 1024 + 2176 + 1792 + 64 + 64 + 256 + 1088)
#define SMEM_BYTES  (SMEM_FLOATS * 4)

__global__ __launch_bounds__(256, 3)
void lnn_kernel(const float* __restrict__ x,
                const float* __restrict__ W1m, const float* __restrict__ b1m,
                const float* __restrict__ W2m, const float* __restrict__ b2m,
                const float* __restrict__ W3m,
                const float* __restrict__ W1q, const float* __restrict__ b1q,
                const float* __restrict__ W2q, const float* __restrict__ b2q,
                const float* __restrict__ W3q,
                float* __restrict__ out)
{
    extern __shared__ float sm[];
    float* Mt    = sm;                 // 8704
    float* Bs    = Mt + 8704;          // 2048
    float* Ast   = Bs + 2048;          // 1024
    float* Hs    = Ast + 1024;         // 2176
    float* h1s   = Hs + 2176;          // 256
    float* aas   = h1s + 256;
    float* sss   = aas + 256;
    float* ccs   = sss + 256;
    float* ees   = ccs + 256;
    float* dds   = ees + 256;
    float* aus   = dds + 256;
    float* xs    = aus + 256;          // 64
    float* gsA   = xs + 64;            // 64
    float* gpart = gsA + 64;           // 256
    float* Sv    = gpart + 256;        // 1088

    const int tid = threadIdx.x;
    const int b   = blockIdx.x;

    for (int q = tid; q < 2176; q += 256) Hs[q] = 0.0f;
    if (tid < 64) { gsA[tid] = 0.0f; xs[tid] = x[b * 64 + tid]; }
    __syncthreads();

    #pragma unroll 1
    for (int pass = 0; pass < 2; pass++) {
        const float* W1  = pass ? W1q : W1m;
        const float* b1  = pass ? b1q : b1m;
        const float* W2  = pass ? W2q : W2m;
        const float* b2  = pass ? b2q : b2m;
        const float* W3  = pass ? W3q : W3m;
        const float* W1T = g_W1T + pass * (DD * HD);
        const float* W2T = g_W2T + pass * (HD * HD);

        // ---- Stage 1: z1 = x W1 + b1 ; h1, a = act', s = act'' ----
        {
            int j = tid;
            float zx = b1[j], zy = 0.f, zz2 = 0.f, zw = 0.f;
            const float4* xv = (const float4*)xs;
            #pragma unroll 4
            for (int i4 = 0; i4 < 16; i4++) {
                float4 v = xv[i4];
                int i = i4 * 4;
                zx = fmaf(v.x, W1[(i + 0) * HD + j], zx);
                zy = fmaf(v.y, W1[(i + 1) * HD + j], zy);
                zz2 = fmaf(v.z, W1[(i + 2) * HD + j], zz2);
                zw = fmaf(v.w, W1[(i + 3) * HD + j], zw);
            }
            float z = (zx + zy) + (zz2 + zw);
            float h, a, s;
            if (pass == 0) {
                float sg = 1.0f / (1.0f + __expf(-z));
                h = fmaxf(z, 0.0f) + log1pf(__expf(-fabsf(z)));
                a = sg;
                s = sg * (1.0f - sg);
            } else {
                float t = tanhf(0.5f * z);
                float o = 1.0f - t * t;
                h = z * t;
                a = fmaf(0.5f * z, o, t);
                s = o * (1.0f - 0.5f * z * t);
            }
            h1s[j] = h; aas[j] = a; sss[j] = s;
        }
        __syncthreads();

        // ---- Stage 2: z2 = h1 W2 + b2 ; c = act'(z2)*w3, e = act''(z2)*w3 ----
        {
            int k = tid;
            float zx = b2[k], zy = 0.f, zz2 = 0.f, zw = 0.f;
            const float4* hv4 = (const float4*)h1s;
            #pragma unroll 4
            for (int l4 = 0; l4 < 64; l4++) {
                float4 v = hv4[l4];
                int l = l4 * 4;
                zx = fmaf(v.x, W2[(l + 0) * HD + k], zx);
                zy = fmaf(v.y, W2[(l + 1) * HD + k], zy);
                zz2 = fmaf(v.z, W2[(l + 2) * HD + k], zz2);
                zw = fmaf(v.w, W2[(l + 3) * HD + k], zw);
            }
            float z = (zx + zy) + (zz2 + zw);
            float a, s;
            if (pass == 0) {
                float sg = 1.0f / (1.0f + __expf(-z));
                a = sg;
                s = sg * (1.0f - sg);
            } else {
                float t = tanhf(0.5f * z);
                float o = 1.0f - t * t;
                a = fmaf(0.5f * z, o, t);
                s = o * (1.0f - 0.5f * z * t);
            }
            float w3v = W3[k];
            ccs[k] = a * w3v;
            ees[k] = s * w3v;
        }
        __syncthreads();

        // ---- Stage 3: u = W2 c ; d = s*u, au = a*u ----
        {
            int j = tid;
            float ux = 0.f, uy = 0.f, uz = 0.f, uw = 0.f;
            const float4* cv4 = (const float4*)ccs;
            #pragma unroll 4
            for (int k4 = 0; k4 < 64; k4++) {
                float4 v = cv4[k4];
                int k = k4 * 4;
                ux = fmaf(v.x, W2T[(k + 0) * HD + j], ux);
                uy = fmaf(v.y, W2T[(k + 1) * HD + j], uy);
                uz = fmaf(v.z, W2T[(k + 2) * HD + j], uz);
                uw = fmaf(v.w, W2T[(k + 3) * HD + j], uw);
            }
            float u = (ux + uy) + (uz + uw);
            dds[j] = sss[j] * u;
            aus[j] = aas[j] * u;
        }
        __syncthreads();

        // ---- Stage 4: gradient g = W1 (a*u), 4-way j-split ----
        {
            int m = tid & 63, part = tid >> 6;
            const float* W1Tp = W1T + part * 64 * 64;
            const float4* av4 = (const float4*)(aus + part * 64);
            float gx = 0.f, gy = 0.f, gz = 0.f, gw = 0.f;
            #pragma unroll 4
            for (int j4 = 0; j4 < 16; j4++) {
                float4 v = av4[j4];
                int jj = j4 * 4;
                gx = fmaf(W1Tp[(jj + 0) * 64 + m], v.x, gx);
                gy = fmaf(W1Tp[(jj + 1) * 64 + m], v.y, gy);
                gz = fmaf(W1Tp[(jj + 2) * 64 + m], v.z, gz);
                gw = fmaf(W1Tp[(jj + 3) * 64 + m], v.w, gw);
            }
            gpart[part * 64 + m] = (gx + gy) + (gz + gw);
        }
        __syncthreads();
        if (tid < 64)
            gsA[tid] += gpart[tid] + gpart[64 + tid] + gpart[128 + tid] + gpart[192 + tid];

        // ---- Stages 5+6 fused: per 128-k tile, M tile GEMM then H2 rank-accum ----
        // H accumulators (persist across tiles): 2-way k-split, 4x4 per thread.
        const int kg = tid >> 7;     // 0..1
        const int s  = tid & 127;
        const int si = s >> 4;       // i block: rows 32 + si*4 .. +3
        const int sj = s & 15;       // j block: cols sj*4 .. +3
        float acc2[4][4];
        #pragma unroll
        for (int i = 0; i < 4; i++)
            #pragma unroll
            for (int j = 0; j < 4; j++) acc2[i][j] = 0.0f;

        const int tk5 = tid >> 4;    // 0..15 : k rows tk5*8 .. +7
        const int tm5 = tid & 15;    // 0..15 : m cols tm5*4 .. +3

        #pragma unroll 1
        for (int ktile = 0; ktile < 2; ktile++) {
            // --- GEMM: Mt[k][m] = sum_j (a_j W1T[j][m]) W2[j][ktile*128 + k] ---
            float acc[8][4];
            #pragma unroll
            for (int i = 0; i < 8; i++)
                #pragma unroll
                for (int j = 0; j < 4; j++) acc[i][j] = 0.0f;

            const float4* W2v  = (const float4*)W2;
            const float4* W1Tv = (const float4*)W1T;
            float4* Bs4  = (float4*)Bs;
            float4* Ast4 = (float4*)Ast;

            for (int jt = 0; jt < 256; jt += 16) {
                #pragma unroll
                for (int r = 0; r < 2; r++) {
                    int f = tid + r * 256;          // 0..511
                    int j = f >> 5, kq = f & 31;
                    Bs4[f] = W2v[(jt + j) * 64 + ktile * 32 + kq];
                }
                {
                    int f = tid;                    // 0..255
                    int j = f >> 4, m4 = f & 15;
                    float4 v = W1Tv[(jt + j) * 16 + m4];
                    float aw = aas[jt + j];
                    v.x *= aw; v.y *= aw; v.z *= aw; v.w *= aw;
                    Ast4[f] = v;
                }
                __syncthreads();
                #pragma unroll
                for (int jj = 0; jj < 16; jj++) {
                    float4 av = Ast4[jj * 16 + tm5];
                    float4 b0 = Bs4[jj * 32 + tk5 * 2];
                    float4 b1 = Bs4[jj * 32 + tk5 * 2 + 1];
                    float am[4] = {av.x, av.y, av.z, av.w};
                    float bk[8] = {b0.x, b0.y, b0.z, b0.w, b1.x, b1.y, b1.z, b1.w};
                    #pragma unroll
                    for (int kk = 0; kk < 8; kk++)
                        #pragma unroll
                        for (int mm = 0; mm < 4; mm++)
                            acc[kk][mm] = fmaf(bk[kk], am[mm], acc[kk][mm]);
                }
                __syncthreads();
            }
            // write Mt tile (conflict-free: 4-phase floor)
            #pragma unroll
            for (int kk = 0; kk < 8; kk++) {
                float4* dst = (float4*)(Mt + (tk5 * 8 + kk) * 68 + tm5 * 4);
                *dst = make_float4(acc[kk][0], acc[kk][1], acc[kk][2], acc[kk][3]);
            }
            __syncthreads();

            // --- H2: acc2 += sum_k e_k * Mt[k][32+i] * Mt[k][j] ---
            #pragma unroll 2
            for (int k = kg; k < 128; k += 2) {
                float w = ees[ktile * 128 + k];
                const float4* Mr = (const float4*)(Mt + k * 68);
                float4 iv = Mr[8 + si];
                float4 jv = Mr[sj];
                float ivw[4] = {iv.x * w, iv.y * w, iv.z * w, iv.w * w};
                float jvv[4] = {jv.x, jv.y, jv.z, jv.w};
                #pragma unroll
                for (int ii = 0; ii < 4; ii++)
                    #pragma unroll
                    for (int jj = 0; jj < 4; jj++)
                        acc2[ii][jj] = fmaf(ivw[ii], jvv[jj], acc2[ii][jj]);
            }
            __syncthreads();   // Mt reused next tile
        }

        // ---- H1: acc2 += sum_k d_k * W1T[k][32+i] * W1T[k][j] ----
        {
            const float4* W1Tv = (const float4*)W1T;
            float4* Ast4 = (float4*)Ast;
            for (int kt = 0; kt < 256; kt += 16) {
                Ast4[tid] = W1Tv[kt * 16 + tid];
                __syncthreads();
                #pragma unroll
                for (int kq = 0; kq < 8; kq++) {
                    int kk = kg * 8 + kq;
                    float w  = dds[kt + kk];
                    float4 iv = Ast4[kk * 16 + 8 + si];
                    float4 jv = Ast4[kk * 16 + sj];
                    float ivw[4] = {iv.x * w, iv.y * w, iv.z * w, iv.w * w};
                    float jvv[4] = {jv.x, jv.y, jv.z, jv.w};
                    #pragma unroll
                    for (int ii = 0; ii < 4; ii++)
                        #pragma unroll
                        for (int jj = 0; jj < 4; jj++)
                            acc2[ii][jj] = fmaf(ivw[ii], jvv[jj], acc2[ii][jj]);
                }
                __syncthreads();
            }
        }

        // ---- reduce the 2 k-groups into Hs (no atomics; Bs free here) ----
        {
            float4* red4 = (float4*)Bs;        // 128 s * 4 float4 = 512 float4
            if (kg == 1) {
                float4* dst = red4 + s * 4;
                #pragma unroll
                for (int ii = 0; ii < 4; ii++)
                    dst[ii] = make_float4(acc2[ii][0], acc2[ii][1], acc2[ii][2], acc2[ii][3]);
            }
            __syncthreads();
            if (kg == 0) {
                const float4* src = red4 + s * 4;
                #pragma unroll
                for (int ii = 0; ii < 4; ii++) {
                    float4 v = src[ii];
                    float* hrow = Hs + (si * 4 + ii) * 68 + sj * 4;
                    float4 h = *(float4*)hrow;
                    *(float4*)hrow = make_float4(h.x + acc2[ii][0] + v.x,
                                                 h.y + acc2[ii][1] + v.y,
                                                 h.z + acc2[ii][2] + v.z,
                                                 h.w + acc2[ii][3] + v.w);
                }
            }
        }
        __syncthreads();
    }

    // ---- Solve: (Hs[:,32:64] + 2I) qdd = g[:32] - Hs[:,0:32] qdot ----
    if (tid < 32) {
        int i = tid;
        float r = gsA[i];
        #pragma unroll 8
        for (int j = 0; j < 32; j++) r -= Hs[i * 68 + j] * xs[32 + j];
        #pragma unroll 8
        for (int j = 0; j < 32; j++)
            Sv[i * 34 + j] = Hs[i * 68 + 32 + j] + ((i == j) ? 2.0f : 0.0f);
        Sv[i * 34 + 32] = r;
    }
    __syncthreads();
    if (tid < 32) {
        int lane = tid;
        for (int p = 0; p < 32; p++) {
            float v = (lane >= p) ? fabsf(Sv[lane * 34 + p]) : -1.0f;
            int idx = lane;
            #pragma unroll
            for (int off = 16; off; off >>= 1) {
                float v2 = __shfl_xor_sync(0xffffffffu, v, off);
                int   i2 = __shfl_xor_sync(0xffffffffu, idx, off);
                if (v2 > v || (v2 == v && i2 < idx)) { v = v2; idx = i2; }
            }
            if (idx != p) {
                float t1 = Sv[p * 34 + lane];
                Sv[p * 34 + lane]   = Sv[idx * 34 + lane];
                Sv[idx * 34 + lane] = t1;
                if (lane == 0) {
                    float t2 = Sv[p * 34 + 32];
                    Sv[p * 34 + 32]   = Sv[idx * 34 + 32];
                    Sv[idx * 34 + 32] = t2;
                }
            }
            __syncwarp();
            float pinvv = 1.0f / Sv[p * 34 + p];
            if (lane != p) {
                float f = Sv[lane * 34 + p] * pinvv;
                for (int c = p; c < 33; c++)
                    Sv[lane * 34 + c] -= f * Sv[p * 34 + c];
            }
            __syncwarp();
        }
        float qdd = Sv[lane * 34 + 32] / Sv[lane * 34 + lane];
        out[b * 64 + lane]      = xs[32 + lane];
        out[b * 64 + 32 + lane] = qdd;
    }
}

extern "C" void kernel_launch(void* const* d_in, const int* in_sizes, int n_in,
                              void* d_out, int out_size)
{
    const float* x   = (const float*)d_in[0];
    const float* W1m = (const float*)d_in[1];
    const float* b1m = (const float*)d_in[2];
    const float* W2m = (const float*)d_in[3];
    const float* b2m = (const float*)d_in[4];
    const float* W3m = (const float*)d_in[5];
    const float* W1q = (const float*)d_in[6];
    const float* b1q = (const float*)d_in[7];
    const float* W2q = (const float*)d_in[8];
    const float* b2q = (const float*)d_in[9];
    const float* W3q = (const float*)d_in[10];
    float* out = (float*)d_out;

    int B = in_sizes[0] / 64;

    prep_kernel<<<256, 256>>>(W1m, W2m, W1q, W2q);
    cudaFuncSetAttribute(lnn_kernel, cudaFuncAttributeMaxDynamicSharedMemorySize, SMEM_BYTES);
    lnn_kernel<<<B, 256, SMEM_BYTES>>>(x, W1m, b1m, W2m, b2m, W3m,
                                       W1q, b1q, W2q, b2q, W3q, out);
}